// round 1
// baseline (speedup 1.0000x reference)
#include <cuda_runtime.h>
#include <cstdint>
#include <cstddef>

// ---------------------------------------------------------------------------
// Problem constants
// ---------------------------------------------------------------------------
constexpr int B    = 2048;
constexpr int S    = 24;
constexpr int T    = 25;
constexpr int H    = 256;
constexpr int E    = 300;
constexpr int VIN  = 64;
constexpr int VOUT = 128;
constexpr int G3   = 768;   // 3*H
constexpr int H2   = 512;   // 2*H

// ---------------------------------------------------------------------------
// Device scratch (static __device__ arrays: allocation-free)
// ---------------------------------------------------------------------------
__device__ float g_emb_gi_f[VIN * G3];        // enc_emb @ enc_Wih_f + bih_f
__device__ float g_emb_gi_b[VIN * G3];        // enc_emb @ enc_Wih_b + bih_b
__device__ float g_dec_gi_emb[VOUT * G3];     // dec_emb @ dec_Wih[0:300] + dec_bih
__device__ float g_dec_logit_emb[VOUT * VOUT];// dec_emb @ fcW[768:1068] + fcb
__device__ float g_Wcat[H * 1024];            // [attn_Wh | dec_Whh], (256,1024)
__device__ float g_bias_cat[1024];            // [attn_b | dec_bhh]
__device__ float g_hf[B * H];
__device__ float g_hb[B * H];
__device__ float g_h[B * H];                  // decoder hidden
__device__ float g_cat512[B * H2];
__device__ float g_enc_out[(size_t)B * S * H2];   // [b][s][512]
__device__ float g_enc_proj[(size_t)B * S * H];   // [b][s][256]
__device__ float g_gh[2 * B * G3];            // encoder recurrent gemm out (f|b)
__device__ float g_g1[B * 1024];              // [hWh+attn_b | gh+bhh]
__device__ float g_gi[B * G3];
__device__ float g_weighted[B * H2];
__device__ float g_xcat[B * G3];              // [hn | weighted]

// ---------------------------------------------------------------------------
// Activations
// ---------------------------------------------------------------------------
__device__ __forceinline__ float tanh_approx(float x) {
    float y;
    asm("tanh.approx.f32 %0, %1;" : "=f"(y) : "f"(x));
    return y;
}
// accurate tanh via fast exp (rel err ~1e-6): safe inside GRU recurrences
__device__ __forceinline__ float tanh_acc(float x) {
    float ax = fabsf(x);
    float t  = __expf(-2.0f * ax);
    float r  = __fdividef(1.0f - t, 1.0f + t);
    return copysignf(r, x);
}
__device__ __forceinline__ float sig_acc(float x) {
    return __fdividef(1.0f, 1.0f + __expf(-x));
}

// ---------------------------------------------------------------------------
// Generic naive GEMM for tiny precompute GEMMs (any K), C = A@B + bias
// A:[M,K] lda, B:[K,N] ldb, C:[M,N] ldc
// ---------------------------------------------------------------------------
__global__ void gemm_naive(const float* __restrict__ A, int lda,
                           const float* __restrict__ Bw, int ldb,
                           float* __restrict__ C, int ldc,
                           int M, int N, int K,
                           const float* __restrict__ bias) {
    int idx = blockIdx.x * blockDim.x + threadIdx.x;
    if (idx >= M * N) return;
    int m = idx / N, n = idx % N;
    float s = bias ? bias[n] : 0.0f;
    for (int k = 0; k < K; k++) s += A[m * lda + k] * Bw[k * ldb + n];
    C[m * ldc + n] = s;
}

// ---------------------------------------------------------------------------
// Tiled fp32 GEMM. Requires M%BM==0, N%BN==0, K%BK==0 (all our shapes comply).
// Epilogue: C = act( acc + bias[n] + gtab[gidx[m]*ldg + n] )
// Optional second problem on blockIdx.z==1 (same M,N,K/ld's).
// ---------------------------------------------------------------------------
template<int BM, int BN, int BK, int TM, int TN>
__global__ __launch_bounds__((BM/TM)*(BN/TN))
void gemm_k(const float* __restrict__ A, int lda,
            const float* __restrict__ Bw, int ldb,
            float* __restrict__ C, int ldc,
            int M, int N, int K,
            const float* __restrict__ bias,
            const float* __restrict__ gtab, const int* __restrict__ gidx, int ldg,
            int act,
            const float* __restrict__ A2, const float* __restrict__ B2,
            float* __restrict__ C2, const float* __restrict__ bias2) {
    constexpr int NT = (BM / TM) * (BN / TN);
    if (blockIdx.z == 1) { A = A2; Bw = B2; C = C2; bias = bias2; }

    __shared__ __align__(16) float As[BK][BM];
    __shared__ __align__(16) float Bs[BK][BN];

    const int tid  = threadIdx.x;
    const int m0   = blockIdx.y * BM;
    const int n0   = blockIdx.x * BN;
    const int tcol = tid % (BN / TN);
    const int trow = tid / (BN / TN);

    float acc[TM][TN];
#pragma unroll
    for (int i = 0; i < TM; i++)
#pragma unroll
        for (int j = 0; j < TN; j++) acc[i][j] = 0.0f;

    for (int k0 = 0; k0 < K; k0 += BK) {
        for (int i = tid; i < BM * BK; i += NT) {
            int m = i / BK, kk = i % BK;
            As[kk][m] = A[(size_t)(m0 + m) * lda + k0 + kk];
        }
        for (int i = tid; i < BK * BN; i += NT) {
            int kk = i / BN, n = i % BN;
            Bs[kk][n] = Bw[(size_t)(k0 + kk) * ldb + n0 + n];
        }
        __syncthreads();
#pragma unroll
        for (int kk = 0; kk < BK; kk++) {
            float a[TM], bv[TN];
#pragma unroll
            for (int i = 0; i < TM; i += 4) {
                float4 v = *reinterpret_cast<const float4*>(&As[kk][trow * TM + i]);
                a[i] = v.x; a[i+1] = v.y; a[i+2] = v.z; a[i+3] = v.w;
            }
#pragma unroll
            for (int j = 0; j < TN; j += 4) {
                float4 v = *reinterpret_cast<const float4*>(&Bs[kk][tcol * TN + j]);
                bv[j] = v.x; bv[j+1] = v.y; bv[j+2] = v.z; bv[j+3] = v.w;
            }
#pragma unroll
            for (int i = 0; i < TM; i++)
#pragma unroll
                for (int j = 0; j < TN; j++) acc[i][j] = fmaf(a[i], bv[j], acc[i][j]);
        }
        __syncthreads();
    }

#pragma unroll
    for (int i = 0; i < TM; i++) {
        int m = m0 + trow * TM + i;
        const float* grow = gtab ? (gtab + (size_t)gidx[m] * ldg) : nullptr;
#pragma unroll
        for (int j = 0; j < TN; j++) {
            int n = n0 + tcol * TN + j;
            float v = acc[i][j];
            if (bias) v += bias[n];
            if (grow) v += grow[n];
            if (act == 1) v = tanh_acc(v);
            C[(size_t)m * ldc + n] = v;
        }
    }
}

// ---------------------------------------------------------------------------
// Weight / bias concat builder for the fused decoder hidden GEMM
// ---------------------------------------------------------------------------
__global__ void build_wcat(const float* __restrict__ Wh,   // (256,256)
                           const float* __restrict__ Whh,  // (256,768)
                           const float* __restrict__ ab,   // (256,)
                           const float* __restrict__ bhh,  // (768,)
                           float* __restrict__ Wcat, float* __restrict__ bias_cat) {
    int idx = blockIdx.x * blockDim.x + threadIdx.x;
    if (idx < H * 1024) {
        int k = idx / 1024, n = idx % 1024;
        Wcat[idx] = (n < H) ? Wh[k * H + n] : Whh[k * G3 + (n - H)];
    }
    if (idx < 1024) bias_cat[idx] = (idx < H) ? ab[idx] : bhh[idx - H];
}

// ---------------------------------------------------------------------------
// Encoder GRU cell (both directions via blockIdx.z)
// gh buffers already contain h@Whh + bhh; gi tables contain x@Wih + bih.
// ---------------------------------------------------------------------------
__global__ void enc_cell(const float* __restrict__ gh_f, const float* __restrict__ gh_b,
                         const float* __restrict__ emb_f, const float* __restrict__ emb_b,
                         const int* __restrict__ src, int s,
                         float* __restrict__ hf, float* __restrict__ hb,
                         float* __restrict__ enc_out) {
    int dir = blockIdx.z;
    int idx = blockIdx.x * blockDim.x + threadIdx.x;   // B*H total
    int b = idx >> 8;
    int h = idx & 255;
    int s_in = dir ? (S - 1 - s) : s;
    int tok  = src[s_in * B + b];
    const float* gh = (dir ? gh_b : gh_f) + (size_t)b * G3;
    const float* gi = (dir ? emb_b : emb_f) + (size_t)tok * G3;
    float* hp = (dir ? hb : hf) + (size_t)b * H + h;
    float r = sig_acc(gi[h] + gh[h]);
    float z = sig_acc(gi[H + h] + gh[H + h]);
    float n = tanh_acc(gi[2 * H + h] + r * gh[2 * H + h]);
    float hprev = *hp;
    float hn = (1.0f - z) * n + z * hprev;
    *hp = hn;
    enc_out[((size_t)b * S + s_in) * H2 + dir * H + h] = hn;
}

// ---------------------------------------------------------------------------
// Decoder GRU cell. gi has emb-gather + bih + weighted@Wih; gh is g1[256:1024].
// Writes new h and the hn slot of xcat.
// ---------------------------------------------------------------------------
__global__ void dec_cell(const float* __restrict__ g1, const float* __restrict__ gi,
                         float* __restrict__ h, float* __restrict__ xcat) {
    int idx = blockIdx.x * blockDim.x + threadIdx.x;
    int b = idx >> 8;
    int hh = idx & 255;
    const float* gh  = g1 + (size_t)b * 1024 + H;
    const float* gip = gi + (size_t)b * G3;
    float r = sig_acc(gip[hh] + gh[hh]);
    float z = sig_acc(gip[H + hh] + gh[H + hh]);
    float n = tanh_acc(gip[2 * H + hh] + r * gh[2 * H + hh]);
    float hprev = h[(size_t)b * H + hh];
    float hn = (1.0f - z) * n + z * hprev;
    h[(size_t)b * H + hh] = hn;
    xcat[(size_t)b * G3 + hh] = hn;
}

// ---------------------------------------------------------------------------
// Attention: one block per batch row.
//   e[s]   = sum_h v[h] * tanh(q[h] + proj[b,s,h])   (q includes attn_b)
//   a      = softmax_s(e)
//   w[d]   = sum_s a[s] * enc_out[b,s,d]
// Writes weighted and xcat[256:768].
// ---------------------------------------------------------------------------
__global__ __launch_bounds__(256)
void attn_k(const float* __restrict__ g1, const float* __restrict__ proj,
            const float* __restrict__ enc_out, const float* __restrict__ v,
            float* __restrict__ weighted, float* __restrict__ xcat) {
    int b = blockIdx.x;
    int tid = threadIdx.x;
    __shared__ float e_sh[S];
    __shared__ float a_sh[S];
    __shared__ float red[8];

    float q  = g1[(size_t)b * 1024 + tid];
    float vv = v[tid];
    const float* prow = proj + (size_t)b * S * H;

    for (int s = 0; s < S; s++) {
        float x = q + prow[s * H + tid];
        float val = vv * tanh_approx(x);
#pragma unroll
        for (int o = 16; o > 0; o >>= 1) val += __shfl_xor_sync(0xffffffffu, val, o);
        if ((tid & 31) == 0) red[tid >> 5] = val;
        __syncthreads();
        if (tid < 8) {
            float r2 = red[tid];
#pragma unroll
            for (int o = 4; o > 0; o >>= 1) r2 += __shfl_xor_sync(0xffu, r2, o);
            if (tid == 0) e_sh[s] = r2;
        }
        __syncthreads();
    }

    if (tid < 32) {
        float x = (tid < S) ? e_sh[tid] : -1e30f;
        float mx = x;
#pragma unroll
        for (int o = 16; o > 0; o >>= 1) mx = fmaxf(mx, __shfl_xor_sync(0xffffffffu, mx, o));
        float ex = (tid < S) ? __expf(x - mx) : 0.0f;
        float sm = ex;
#pragma unroll
        for (int o = 16; o > 0; o >>= 1) sm += __shfl_xor_sync(0xffffffffu, sm, o);
        if (tid < S) a_sh[tid] = __fdividef(ex, sm);
    }
    __syncthreads();

    const float* orow = enc_out + (size_t)b * S * H2;
    for (int d = tid; d < H2; d += 256) {
        float acc = 0.0f;
#pragma unroll
        for (int s = 0; s < S; s++) acc = fmaf(a_sh[s], orow[s * H2 + d], acc);
        weighted[(size_t)b * H2 + d] = acc;
        xcat[(size_t)b * G3 + H + d] = acc;
    }
}

__global__ void concat_h(const float* __restrict__ hf, const float* __restrict__ hb,
                         float* __restrict__ cat) {
    int idx = blockIdx.x * blockDim.x + threadIdx.x;   // B*512
    int b = idx >> 9, j = idx & 511;
    cat[idx] = (j < H) ? hf[b * H + j] : hb[b * H + (j - H)];
}

// ---------------------------------------------------------------------------
// Host-side launch helpers
// ---------------------------------------------------------------------------
static void gemm128(const float* A, int lda, const float* Bw, int ldb,
                    float* C, int ldc, int M, int N, int K,
                    const float* bias, const float* gtab, const int* gidx, int ldg,
                    int act,
                    const float* A2 = nullptr, const float* B2 = nullptr,
                    float* C2 = nullptr, const float* bias2 = nullptr) {
    dim3 g(N / 128, M / 128, A2 ? 2 : 1);
    gemm_k<128, 128, 16, 8, 8><<<g, 256>>>(A, lda, Bw, ldb, C, ldc, M, N, K,
                                           bias, gtab, gidx, ldg, act, A2, B2, C2, bias2);
}
static void gemm64(const float* A, int lda, const float* Bw, int ldb,
                   float* C, int ldc, int M, int N, int K,
                   const float* bias, const float* gtab, const int* gidx, int ldg,
                   int act) {
    dim3 g(N / 64, M / 64, 1);
    gemm_k<64, 64, 16, 4, 4><<<g, 256>>>(A, lda, Bw, ldb, C, ldc, M, N, K,
                                         bias, gtab, gidx, ldg, act,
                                         nullptr, nullptr, nullptr, nullptr);
}

extern "C" void kernel_launch(void* const* d_in, const int* in_sizes, int n_in,
                              void* d_out, int out_size) {
    const int*   src       = (const int*)  d_in[0];
    const int*   trg       = (const int*)  d_in[1];
    const float* enc_emb   = (const float*)d_in[2];
    const float* enc_Wih_f = (const float*)d_in[3];
    const float* enc_Whh_f = (const float*)d_in[4];
    const float* enc_bih_f = (const float*)d_in[5];
    const float* enc_bhh_f = (const float*)d_in[6];
    const float* enc_Wih_b = (const float*)d_in[7];
    const float* enc_Whh_b = (const float*)d_in[8];
    const float* enc_bih_b = (const float*)d_in[9];
    const float* enc_bhh_b = (const float*)d_in[10];
    const float* enc_fcW   = (const float*)d_in[11];
    const float* enc_fcb   = (const float*)d_in[12];
    const float* attn_Wh   = (const float*)d_in[13];
    const float* attn_We   = (const float*)d_in[14];
    const float* attn_b    = (const float*)d_in[15];
    const float* attn_v    = (const float*)d_in[16];
    const float* dec_emb   = (const float*)d_in[17];
    const float* dec_Wih   = (const float*)d_in[18];
    const float* dec_Whh   = (const float*)d_in[19];
    const float* dec_bih   = (const float*)d_in[20];
    const float* dec_bhh   = (const float*)d_in[21];
    const float* fcW       = (const float*)d_in[22];
    const float* fcb       = (const float*)d_in[23];
    float* out = (float*)d_out;

    // resolve scratch pointers (host-side query; capture-safe)
    float *p_emb_gi_f, *p_emb_gi_b, *p_dec_gi_emb, *p_dec_logit_emb;
    float *p_Wcat, *p_bias_cat, *p_hf, *p_hb, *p_h, *p_cat512;
    float *p_enc_out, *p_enc_proj, *p_gh, *p_g1, *p_gi, *p_weighted, *p_xcat;
    void* tmp;
    cudaGetSymbolAddress(&tmp, g_emb_gi_f);     p_emb_gi_f    = (float*)tmp;
    cudaGetSymbolAddress(&tmp, g_emb_gi_b);     p_emb_gi_b    = (float*)tmp;
    cudaGetSymbolAddress(&tmp, g_dec_gi_emb);   p_dec_gi_emb  = (float*)tmp;
    cudaGetSymbolAddress(&tmp, g_dec_logit_emb);p_dec_logit_emb=(float*)tmp;
    cudaGetSymbolAddress(&tmp, g_Wcat);         p_Wcat        = (float*)tmp;
    cudaGetSymbolAddress(&tmp, g_bias_cat);     p_bias_cat    = (float*)tmp;
    cudaGetSymbolAddress(&tmp, g_hf);           p_hf          = (float*)tmp;
    cudaGetSymbolAddress(&tmp, g_hb);           p_hb          = (float*)tmp;
    cudaGetSymbolAddress(&tmp, g_h);            p_h           = (float*)tmp;
    cudaGetSymbolAddress(&tmp, g_cat512);       p_cat512      = (float*)tmp;
    cudaGetSymbolAddress(&tmp, g_enc_out);      p_enc_out     = (float*)tmp;
    cudaGetSymbolAddress(&tmp, g_enc_proj);     p_enc_proj    = (float*)tmp;
    cudaGetSymbolAddress(&tmp, g_gh);           p_gh          = (float*)tmp;
    cudaGetSymbolAddress(&tmp, g_g1);           p_g1          = (float*)tmp;
    cudaGetSymbolAddress(&tmp, g_gi);           p_gi          = (float*)tmp;
    cudaGetSymbolAddress(&tmp, g_weighted);     p_weighted    = (float*)tmp;
    cudaGetSymbolAddress(&tmp, g_xcat);         p_xcat        = (float*)tmp;

    // ---- precompute tables (tiny GEMMs, all K=300) ----
    gemm_naive<<<(VIN * G3 + 255) / 256, 256>>>(enc_emb, E, enc_Wih_f, G3,
                                                p_emb_gi_f, G3, VIN, G3, E, enc_bih_f);
    gemm_naive<<<(VIN * G3 + 255) / 256, 256>>>(enc_emb, E, enc_Wih_b, G3,
                                                p_emb_gi_b, G3, VIN, G3, E, enc_bih_b);
    gemm_naive<<<(VOUT * G3 + 255) / 256, 256>>>(dec_emb, E, dec_Wih, G3,
                                                 p_dec_gi_emb, G3, VOUT, G3, E, dec_bih);
    gemm_naive<<<(VOUT * VOUT + 255) / 256, 256>>>(dec_emb, E, fcW + (size_t)G3 * VOUT, VOUT,
                                                   p_dec_logit_emb, VOUT, VOUT, VOUT, E, fcb);
    build_wcat<<<(H * 1024 + 255) / 256, 256>>>(attn_Wh, dec_Whh, attn_b, dec_bhh,
                                                p_Wcat, p_bias_cat);
    cudaMemsetAsync(p_hf, 0, (size_t)B * H * sizeof(float));
    cudaMemsetAsync(p_hb, 0, (size_t)B * H * sizeof(float));
    cudaMemsetAsync(out, 0, (size_t)B * VOUT * sizeof(float));  // t = 0 zeros

    // ---- encoder: 24 steps, fwd+bwd fused via grid.z ----
    for (int s = 0; s < S; s++) {
        gemm128(p_hf, H, enc_Whh_f, G3, p_gh, G3, B, G3, H,
                enc_bhh_f, nullptr, nullptr, 0, 0,
                p_hb, enc_Whh_b, p_gh + (size_t)B * G3, enc_bhh_b);
        enc_cell<<<dim3(B * H / 256, 1, 2), 256>>>(p_gh, p_gh + (size_t)B * G3,
                                                   p_emb_gi_f, p_emb_gi_b,
                                                   src, s, p_hf, p_hb, p_enc_out);
    }

    // ---- decoder init hidden = tanh([hf|hb] @ enc_fcW + enc_fcb) ----
    concat_h<<<B * H2 / 256, 256>>>(p_hf, p_hb, p_cat512);
    gemm64(p_cat512, H2, enc_fcW, H, p_h, H, B, H, H2, enc_fcb,
           nullptr, nullptr, 0, /*tanh*/1);

    // ---- enc_proj = enc_out @ attn_We ----
    gemm128(p_enc_out, H2, attn_We, H, p_enc_proj, H, B * S, H, H2,
            nullptr, nullptr, nullptr, 0, 0);

    // ---- decoder: 24 steps ----
    for (int t = 0; t < T - 1; t++) {
        const int* tok = trg + t * B;
        // [hWh+attn_b | h@Whh+bhh]
        gemm128(p_h, H, p_Wcat, 1024, p_g1, 1024, B, 1024, H,
                p_bias_cat, nullptr, nullptr, 0, 0);
        // attention -> weighted (+xcat[256:768])
        attn_k<<<B, 256>>>(p_g1, p_enc_proj, p_enc_out, attn_v, p_weighted, p_xcat);
        // gi = weighted @ dec_Wih[300:812] + table[trg[t]] (emb part + bih)
        gemm128(p_weighted, H2, dec_Wih + (size_t)E * G3, G3, p_gi, G3, B, G3, H2,
                nullptr, p_dec_gi_emb, tok, G3, 0);
        // GRU cell -> h, xcat[0:256]
        dec_cell<<<B * H / 256, 256>>>(p_g1, p_gi, p_h, p_xcat);
        // logits = xcat @ fcW[0:768] + table[trg[t]] (emb part + fcb)
        gemm64(p_xcat, G3, fcW, VOUT, out + (size_t)(t + 1) * B * VOUT, VOUT,
               B, VOUT, G3, nullptr, p_dec_logit_emb, tok, VOUT, 0);
    }
}

// round 2
// speedup vs baseline: 1.6267x; 1.6267x over previous
#include <cuda_runtime.h>
#include <cstdint>
#include <cstddef>

// ---------------------------------------------------------------------------
// Problem constants
// ---------------------------------------------------------------------------
constexpr int B    = 2048;
constexpr int S    = 24;
constexpr int T    = 25;
constexpr int H    = 256;
constexpr int E    = 300;
constexpr int VIN  = 64;
constexpr int VOUT = 128;
constexpr int G3   = 768;   // 3*H
constexpr int H2   = 512;   // 2*H

// ---------------------------------------------------------------------------
// Device scratch (static __device__ arrays: allocation-free)
// ---------------------------------------------------------------------------
__device__ float g_emb_gi_f[VIN * G3];
__device__ float g_emb_gi_b[VIN * G3];
__device__ float g_dec_gi_emb[VOUT * G3];
__device__ float g_dec_logit_emb[VOUT * VOUT];
__device__ float g_Wcat[H * 1024];
__device__ float g_bias_cat[1024];
__device__ float g_hf[B * H];
__device__ float g_hb[B * H];
__device__ float g_h[B * H];
__device__ float g_cat512[B * H2];
__device__ float g_enc_out[(size_t)B * S * H2];
__device__ float g_enc_proj[(size_t)B * S * H];
__device__ float g_gh[2 * B * G3];
__device__ float g_g1[B * 1024];
__device__ float g_gi[B * G3];
__device__ float g_weighted[B * H2];
__device__ float g_xcat[B * G3];

// ---------------------------------------------------------------------------
// Activations
// ---------------------------------------------------------------------------
__device__ __forceinline__ float tanh_approx(float x) {
    float y;
    asm("tanh.approx.f32 %0, %1;" : "=f"(y) : "f"(x));
    return y;
}
__device__ __forceinline__ float tanh_acc(float x) {
    float ax = fabsf(x);
    float t  = __expf(-2.0f * ax);
    float r  = __fdividef(1.0f - t, 1.0f + t);
    return copysignf(r, x);
}
__device__ __forceinline__ float sig_acc(float x) {
    return __fdividef(1.0f, 1.0f + __expf(-x));
}

// ---------------------------------------------------------------------------
// Tiny naive GEMM for the precompute tables (K=300 etc.)
// ---------------------------------------------------------------------------
__global__ void gemm_naive(const float* __restrict__ A, int lda,
                           const float* __restrict__ Bw, int ldb,
                           float* __restrict__ C, int ldc,
                           int M, int N, int K,
                           const float* __restrict__ bias) {
    int idx = blockIdx.x * blockDim.x + threadIdx.x;
    if (idx >= M * N) return;
    int m = idx / N, n = idx % N;
    float s = bias ? bias[n] : 0.0f;
    for (int k = 0; k < K; k++) s += A[m * lda + k] * Bw[k * ldb + n];
    C[m * ldc + n] = s;
}

// ---------------------------------------------------------------------------
// Main tiled GEMM v2: FFMA2 (fma.rn.f32x2) inner loop + register-staged
// double-buffered shared memory. Requires M%BM==0, N%BN==0, K%BK==0, TN even.
// Epilogue: C = act( acc + bias[n] + gtab[gidx[m]*ldg + n] )
// blockIdx.z==1 switches to a second identically-shaped problem.
// ---------------------------------------------------------------------------
template<int BM, int BN, int BK, int TM, int TN>
__global__ __launch_bounds__((BM/TM)*(BN/TN))
void gemm_k(const float* __restrict__ A, int lda,
            const float* __restrict__ Bw, int ldb,
            float* __restrict__ C, int ldc,
            int M, int N, int K,
            const float* __restrict__ bias,
            const float* __restrict__ gtab, const int* __restrict__ gidx, int ldg,
            int act,
            const float* __restrict__ A2, const float* __restrict__ B2,
            float* __restrict__ C2, const float* __restrict__ bias2) {
    constexpr int NT  = (BM / TM) * (BN / TN);
    constexpr int LA4 = (BM * BK) / (NT * 4);   // float4 A loads per thread
    constexpr int LB4 = (BK * BN) / (NT * 4);   // float4 B loads per thread
    constexpr int BMP = BM + 4;                 // pad to soften transpose-STS conflicts
    static_assert(LA4 >= 1 && LB4 >= 1, "tile too small");

    if (blockIdx.z == 1) { A = A2; Bw = B2; C = C2; bias = bias2; }

    __shared__ __align__(16) float As[2][BK][BMP];
    __shared__ __align__(16) float Bs[2][BK][BN];

    const int tid  = threadIdx.x;
    const int m0   = blockIdx.y * BM;
    const int n0   = blockIdx.x * BN;
    const int tcol = tid % (BN / TN);
    const int trow = tid / (BN / TN);

    float4 ra[LA4], rb[LB4];

    auto ldg_tile = [&](int k0) {
#pragma unroll
        for (int l = 0; l < LA4; l++) {
            int idx = tid + l * NT;
            int m = idx / (BK / 4), kq = idx % (BK / 4);
            ra[l] = *reinterpret_cast<const float4*>(&A[(size_t)(m0 + m) * lda + k0 + kq * 4]);
        }
#pragma unroll
        for (int l = 0; l < LB4; l++) {
            int idx = tid + l * NT;
            int kk = idx / (BN / 4), nq = idx % (BN / 4);
            rb[l] = *reinterpret_cast<const float4*>(&Bw[(size_t)(k0 + kk) * ldb + n0 + nq * 4]);
        }
    };
    auto sts_tile = [&](int buf) {
#pragma unroll
        for (int l = 0; l < LA4; l++) {
            int idx = tid + l * NT;
            int m = idx / (BK / 4), kq = idx % (BK / 4);
            As[buf][kq * 4 + 0][m] = ra[l].x;
            As[buf][kq * 4 + 1][m] = ra[l].y;
            As[buf][kq * 4 + 2][m] = ra[l].z;
            As[buf][kq * 4 + 3][m] = ra[l].w;
        }
#pragma unroll
        for (int l = 0; l < LB4; l++) {
            int idx = tid + l * NT;
            int kk = idx / (BN / 4), nq = idx % (BN / 4);
            *reinterpret_cast<float4*>(&Bs[buf][kk][nq * 4]) = rb[l];
        }
    };

    unsigned long long acc[TM][TN / 2];
#pragma unroll
    for (int i = 0; i < TM; i++)
#pragma unroll
        for (int j = 0; j < TN / 2; j++) acc[i][j] = 0ULL;   // two packed 0.0f

    ldg_tile(0);
    sts_tile(0);
    __syncthreads();

    const int nt = K / BK;
    for (int t = 0; t < nt; t++) {
        const int cur = t & 1;
        if (t + 1 < nt) ldg_tile((t + 1) * BK);

#pragma unroll
        for (int kk = 0; kk < BK; kk++) {
            float a[TM];
            unsigned long long b2[TN / 2];
#pragma unroll
            for (int i = 0; i < TM; i += 4) {
                float4 v = *reinterpret_cast<const float4*>(&As[cur][kk][trow * TM + i]);
                a[i + 0] = v.x; a[i + 1] = v.y; a[i + 2] = v.z; a[i + 3] = v.w;
            }
#pragma unroll
            for (int j = 0; j < TN; j += 4) {
                ulonglong2 v = *reinterpret_cast<const ulonglong2*>(&Bs[cur][kk][tcol * TN + j]);
                b2[j / 2]     = v.x;
                b2[j / 2 + 1] = v.y;
            }
#pragma unroll
            for (int i = 0; i < TM; i++) {
                unsigned long long a2;
                asm("mov.b64 %0, {%1, %1};" : "=l"(a2) : "f"(a[i]));
#pragma unroll
                for (int jj = 0; jj < TN / 2; jj++)
                    asm("fma.rn.f32x2 %0, %1, %2, %0;"
                        : "+l"(acc[i][jj]) : "l"(a2), "l"(b2[jj]));
            }
        }

        if (t + 1 < nt) sts_tile((t + 1) & 1);
        __syncthreads();
    }

#pragma unroll
    for (int i = 0; i < TM; i++) {
        int m = m0 + trow * TM + i;
        const float* grow = gtab ? (gtab + (size_t)gidx[m] * ldg) : nullptr;
#pragma unroll
        for (int jj = 0; jj < TN / 2; jj++) {
            float v0, v1;
            asm("mov.b64 {%0, %1}, %2;" : "=f"(v0), "=f"(v1) : "l"(acc[i][jj]));
            int n = n0 + tcol * TN + jj * 2;
            if (bias) { v0 += bias[n]; v1 += bias[n + 1]; }
            if (grow) { v0 += grow[n]; v1 += grow[n + 1]; }
            if (act == 1) { v0 = tanh_acc(v0); v1 = tanh_acc(v1); }
            *reinterpret_cast<float2*>(&C[(size_t)m * ldc + n]) = make_float2(v0, v1);
        }
    }
}

// ---------------------------------------------------------------------------
// Weight / bias concat builder for the fused decoder hidden GEMM
// ---------------------------------------------------------------------------
__global__ void build_wcat(const float* __restrict__ Wh,
                           const float* __restrict__ Whh,
                           const float* __restrict__ ab,
                           const float* __restrict__ bhh,
                           float* __restrict__ Wcat, float* __restrict__ bias_cat) {
    int idx = blockIdx.x * blockDim.x + threadIdx.x;
    if (idx < H * 1024) {
        int k = idx / 1024, n = idx % 1024;
        Wcat[idx] = (n < H) ? Wh[k * H + n] : Whh[k * G3 + (n - H)];
    }
    if (idx < 1024) bias_cat[idx] = (idx < H) ? ab[idx] : bhh[idx - H];
}

// ---------------------------------------------------------------------------
// Encoder GRU cell (both directions via blockIdx.z)
// ---------------------------------------------------------------------------
__global__ void enc_cell(const float* __restrict__ gh_f, const float* __restrict__ gh_b,
                         const float* __restrict__ emb_f, const float* __restrict__ emb_b,
                         const int* __restrict__ src, int s,
                         float* __restrict__ hf, float* __restrict__ hb,
                         float* __restrict__ enc_out) {
    int dir = blockIdx.z;
    int idx = blockIdx.x * blockDim.x + threadIdx.x;
    int b = idx >> 8;
    int h = idx & 255;
    int s_in = dir ? (S - 1 - s) : s;
    int tok  = src[s_in * B + b];
    const float* gh = (dir ? gh_b : gh_f) + (size_t)b * G3;
    const float* gi = (dir ? emb_b : emb_f) + (size_t)tok * G3;
    float* hp = (dir ? hb : hf) + (size_t)b * H + h;
    float r = sig_acc(gi[h] + gh[h]);
    float z = sig_acc(gi[H + h] + gh[H + h]);
    float n = tanh_acc(gi[2 * H + h] + r * gh[2 * H + h]);
    float hprev = *hp;
    float hn = (1.0f - z) * n + z * hprev;
    *hp = hn;
    enc_out[((size_t)b * S + s_in) * H2 + dir * H + h] = hn;
}

// ---------------------------------------------------------------------------
// Decoder GRU cell
// ---------------------------------------------------------------------------
__global__ void dec_cell(const float* __restrict__ g1, const float* __restrict__ gi,
                         float* __restrict__ h, float* __restrict__ xcat) {
    int idx = blockIdx.x * blockDim.x + threadIdx.x;
    int b = idx >> 8;
    int hh = idx & 255;
    const float* gh  = g1 + (size_t)b * 1024 + H;
    const float* gip = gi + (size_t)b * G3;
    float r = sig_acc(gip[hh] + gh[hh]);
    float z = sig_acc(gip[H + hh] + gh[H + hh]);
    float n = tanh_acc(gip[2 * H + hh] + r * gh[2 * H + hh]);
    float hprev = h[(size_t)b * H + hh];
    float hn = (1.0f - z) * n + z * hprev;
    h[(size_t)b * H + hh] = hn;
    xcat[(size_t)b * G3 + hh] = hn;
}

// ---------------------------------------------------------------------------
// Attention: one block per batch row
// ---------------------------------------------------------------------------
__global__ __launch_bounds__(256)
void attn_k(const float* __restrict__ g1, const float* __restrict__ proj,
            const float* __restrict__ enc_out, const float* __restrict__ v,
            float* __restrict__ weighted, float* __restrict__ xcat) {
    int b = blockIdx.x;
    int tid = threadIdx.x;
    __shared__ float e_sh[S];
    __shared__ float a_sh[S];
    __shared__ float red[8];

    float q  = g1[(size_t)b * 1024 + tid];
    float vv = v[tid];
    const float* prow = proj + (size_t)b * S * H;

    for (int s = 0; s < S; s++) {
        float x = q + prow[s * H + tid];
        float val = vv * tanh_approx(x);
#pragma unroll
        for (int o = 16; o > 0; o >>= 1) val += __shfl_xor_sync(0xffffffffu, val, o);
        if ((tid & 31) == 0) red[tid >> 5] = val;
        __syncthreads();
        if (tid < 8) {
            float r2 = red[tid];
#pragma unroll
            for (int o = 4; o > 0; o >>= 1) r2 += __shfl_xor_sync(0xffu, r2, o);
            if (tid == 0) e_sh[s] = r2;
        }
        __syncthreads();
    }

    if (tid < 32) {
        float x = (tid < S) ? e_sh[tid] : -1e30f;
        float mx = x;
#pragma unroll
        for (int o = 16; o > 0; o >>= 1) mx = fmaxf(mx, __shfl_xor_sync(0xffffffffu, mx, o));
        float ex = (tid < S) ? __expf(x - mx) : 0.0f;
        float sm = ex;
#pragma unroll
        for (int o = 16; o > 0; o >>= 1) sm += __shfl_xor_sync(0xffffffffu, sm, o);
        if (tid < S) a_sh[tid] = __fdividef(ex, sm);
    }
    __syncthreads();

    const float* orow = enc_out + (size_t)b * S * H2;
    for (int d = tid; d < H2; d += 256) {
        float acc = 0.0f;
#pragma unroll
        for (int s = 0; s < S; s++) acc = fmaf(a_sh[s], orow[s * H2 + d], acc);
        weighted[(size_t)b * H2 + d] = acc;
        xcat[(size_t)b * G3 + H + d] = acc;
    }
}

__global__ void concat_h(const float* __restrict__ hf, const float* __restrict__ hb,
                         float* __restrict__ cat) {
    int idx = blockIdx.x * blockDim.x + threadIdx.x;
    int b = idx >> 9, j = idx & 511;
    cat[idx] = (j < H) ? hf[b * H + j] : hb[b * H + (j - H)];
}

// ---------------------------------------------------------------------------
// Host-side launch helpers
// ---------------------------------------------------------------------------
static void gemm128(const float* A, int lda, const float* Bw, int ldb,
                    float* C, int ldc, int M, int N, int K,
                    const float* bias, const float* gtab, const int* gidx, int ldg,
                    int act,
                    const float* A2 = nullptr, const float* B2 = nullptr,
                    float* C2 = nullptr, const float* bias2 = nullptr) {
    dim3 g(N / 128, M / 128, A2 ? 2 : 1);
    gemm_k<128, 128, 16, 8, 8><<<g, 256>>>(A, lda, Bw, ldb, C, ldc, M, N, K,
                                           bias, gtab, gidx, ldg, act, A2, B2, C2, bias2);
}
static void gemm64(const float* A, int lda, const float* Bw, int ldb,
                   float* C, int ldc, int M, int N, int K,
                   const float* bias, const float* gtab, const int* gidx, int ldg,
                   int act) {
    dim3 g(N / 64, M / 64, 1);
    gemm_k<64, 64, 16, 4, 4><<<g, 256>>>(A, lda, Bw, ldb, C, ldc, M, N, K,
                                         bias, gtab, gidx, ldg, act,
                                         nullptr, nullptr, nullptr, nullptr);
}
static void gemm32(const float* A, int lda, const float* Bw, int ldb,
                   float* C, int ldc, int M, int N, int K,
                   const float* bias, const float* gtab, const int* gidx, int ldg,
                   int act) {
    dim3 g(N / 64, M / 32, 1);
    gemm_k<32, 64, 16, 4, 4><<<g, 128>>>(A, lda, Bw, ldb, C, ldc, M, N, K,
                                         bias, gtab, gidx, ldg, act,
                                         nullptr, nullptr, nullptr, nullptr);
}

extern "C" void kernel_launch(void* const* d_in, const int* in_sizes, int n_in,
                              void* d_out, int out_size) {
    const int*   src       = (const int*)  d_in[0];
    const int*   trg       = (const int*)  d_in[1];
    const float* enc_emb   = (const float*)d_in[2];
    const float* enc_Wih_f = (const float*)d_in[3];
    const float* enc_Whh_f = (const float*)d_in[4];
    const float* enc_bih_f = (const float*)d_in[5];
    const float* enc_bhh_f = (const float*)d_in[6];
    const float* enc_Wih_b = (const float*)d_in[7];
    const float* enc_Whh_b = (const float*)d_in[8];
    const float* enc_bih_b = (const float*)d_in[9];
    const float* enc_bhh_b = (const float*)d_in[10];
    const float* enc_fcW   = (const float*)d_in[11];
    const float* enc_fcb   = (const float*)d_in[12];
    const float* attn_Wh   = (const float*)d_in[13];
    const float* attn_We   = (const float*)d_in[14];
    const float* attn_b    = (const float*)d_in[15];
    const float* attn_v    = (const float*)d_in[16];
    const float* dec_emb   = (const float*)d_in[17];
    const float* dec_Wih   = (const float*)d_in[18];
    const float* dec_Whh   = (const float*)d_in[19];
    const float* dec_bih   = (const float*)d_in[20];
    const float* dec_bhh   = (const float*)d_in[21];
    const float* fcW       = (const float*)d_in[22];
    const float* fcb       = (const float*)d_in[23];
    float* out = (float*)d_out;

    float *p_emb_gi_f, *p_emb_gi_b, *p_dec_gi_emb, *p_dec_logit_emb;
    float *p_Wcat, *p_bias_cat, *p_hf, *p_hb, *p_h, *p_cat512;
    float *p_enc_out, *p_enc_proj, *p_gh, *p_g1, *p_gi, *p_weighted, *p_xcat;
    void* tmp;
    cudaGetSymbolAddress(&tmp, g_emb_gi_f);      p_emb_gi_f     = (float*)tmp;
    cudaGetSymbolAddress(&tmp, g_emb_gi_b);      p_emb_gi_b     = (float*)tmp;
    cudaGetSymbolAddress(&tmp, g_dec_gi_emb);    p_dec_gi_emb   = (float*)tmp;
    cudaGetSymbolAddress(&tmp, g_dec_logit_emb); p_dec_logit_emb= (float*)tmp;
    cudaGetSymbolAddress(&tmp, g_Wcat);          p_Wcat         = (float*)tmp;
    cudaGetSymbolAddress(&tmp, g_bias_cat);      p_bias_cat     = (float*)tmp;
    cudaGetSymbolAddress(&tmp, g_hf);            p_hf           = (float*)tmp;
    cudaGetSymbolAddress(&tmp, g_hb);            p_hb           = (float*)tmp;
    cudaGetSymbolAddress(&tmp, g_h);             p_h            = (float*)tmp;
    cudaGetSymbolAddress(&tmp, g_cat512);        p_cat512       = (float*)tmp;
    cudaGetSymbolAddress(&tmp, g_enc_out);       p_enc_out      = (float*)tmp;
    cudaGetSymbolAddress(&tmp, g_enc_proj);      p_enc_proj     = (float*)tmp;
    cudaGetSymbolAddress(&tmp, g_gh);            p_gh           = (float*)tmp;
    cudaGetSymbolAddress(&tmp, g_g1);            p_g1           = (float*)tmp;
    cudaGetSymbolAddress(&tmp, g_gi);            p_gi           = (float*)tmp;
    cudaGetSymbolAddress(&tmp, g_weighted);      p_weighted     = (float*)tmp;
    cudaGetSymbolAddress(&tmp, g_xcat);          p_xcat         = (float*)tmp;

    // ---- precompute tables ----
    gemm_naive<<<(VIN * G3 + 255) / 256, 256>>>(enc_emb, E, enc_Wih_f, G3,
                                                p_emb_gi_f, G3, VIN, G3, E, enc_bih_f);
    gemm_naive<<<(VIN * G3 + 255) / 256, 256>>>(enc_emb, E, enc_Wih_b, G3,
                                                p_emb_gi_b, G3, VIN, G3, E, enc_bih_b);
    gemm_naive<<<(VOUT * G3 + 255) / 256, 256>>>(dec_emb, E, dec_Wih, G3,
                                                 p_dec_gi_emb, G3, VOUT, G3, E, dec_bih);
    gemm_naive<<<(VOUT * VOUT + 255) / 256, 256>>>(dec_emb, E, fcW + (size_t)G3 * VOUT, VOUT,
                                                   p_dec_logit_emb, VOUT, VOUT, VOUT, E, fcb);
    build_wcat<<<(H * 1024 + 255) / 256, 256>>>(attn_Wh, dec_Whh, attn_b, dec_bhh,
                                                p_Wcat, p_bias_cat);
    cudaMemsetAsync(p_hf, 0, (size_t)B * H * sizeof(float));
    cudaMemsetAsync(p_hb, 0, (size_t)B * H * sizeof(float));
    cudaMemsetAsync(out, 0, (size_t)B * VOUT * sizeof(float));

    // ---- encoder: 24 steps, fwd+bwd fused via grid.z ----
    for (int s = 0; s < S; s++) {
        gemm128(p_hf, H, enc_Whh_f, G3, p_gh, G3, B, G3, H,
                enc_bhh_f, nullptr, nullptr, 0, 0,
                p_hb, enc_Whh_b, p_gh + (size_t)B * G3, enc_bhh_b);
        enc_cell<<<dim3(B * H / 256, 1, 2), 256>>>(p_gh, p_gh + (size_t)B * G3,
                                                   p_emb_gi_f, p_emb_gi_b,
                                                   src, s, p_hf, p_hb, p_enc_out);
    }

    // ---- decoder init hidden ----
    concat_h<<<B * H2 / 256, 256>>>(p_hf, p_hb, p_cat512);
    gemm64(p_cat512, H2, enc_fcW, H, p_h, H, B, H, H2, enc_fcb,
           nullptr, nullptr, 0, /*tanh*/1);

    // ---- enc_proj = enc_out @ attn_We ----
    gemm128(p_enc_out, H2, attn_We, H, p_enc_proj, H, B * S, H, H2,
            nullptr, nullptr, nullptr, 0, 0);

    // ---- decoder: 24 steps ----
    for (int t = 0; t < T - 1; t++) {
        const int* tok = trg + t * B;
        gemm128(p_h, H, p_Wcat, 1024, p_g1, 1024, B, 1024, H,
                p_bias_cat, nullptr, nullptr, 0, 0);
        attn_k<<<B, 256>>>(p_g1, p_enc_proj, p_enc_out, attn_v, p_weighted, p_xcat);
        gemm128(p_weighted, H2, dec_Wih + (size_t)E * G3, G3, p_gi, G3, B, G3, H2,
                nullptr, p_dec_gi_emb, tok, G3, 0);
        dec_cell<<<B * H / 256, 256>>>(p_g1, p_gi, p_h, p_xcat);
        gemm32(p_xcat, G3, fcW, VOUT, out + (size_t)(t + 1) * B * VOUT, VOUT,
               B, VOUT, G3, nullptr, p_dec_logit_emb, tok, VOUT, 0);
    }
}

// round 3
// speedup vs baseline: 1.6690x; 1.0260x over previous
#include <cuda_runtime.h>
#include <cstdint>
#include <cstddef>

// ---------------------------------------------------------------------------
// Problem constants
// ---------------------------------------------------------------------------
constexpr int B    = 2048;
constexpr int S    = 24;
constexpr int T    = 25;
constexpr int H    = 256;
constexpr int E    = 300;
constexpr int VIN  = 64;
constexpr int VOUT = 128;
constexpr int G3   = 768;   // 3*H
constexpr int H2   = 512;   // 2*H

// ---------------------------------------------------------------------------
// Device scratch (static __device__ arrays: allocation-free)
// ---------------------------------------------------------------------------
__device__ float g_emb_gi_f[VIN * G3];
__device__ float g_emb_gi_b[VIN * G3];
__device__ float g_dec_gi_emb[VOUT * G3];
__device__ float g_dec_logit_emb[VOUT * VOUT];
__device__ float g_Wcat[H * 1024];
__device__ float g_bias_cat[1024];
__device__ float g_hf[B * H];
__device__ float g_hb[B * H];
__device__ float g_h[B * H];
__device__ float g_cat512[B * H2];
__device__ float g_enc_out[(size_t)B * S * H2];
__device__ float g_enc_proj[(size_t)B * S * H];
__device__ float g_gh[2 * B * G3];
__device__ float g_g1[B * 1024];
__device__ float g_gi[B * G3];
__device__ float g_weighted[B * H2];
__device__ float g_xcat[B * G3];

// ---------------------------------------------------------------------------
// Activations
// ---------------------------------------------------------------------------
__device__ __forceinline__ float tanh_approx(float x) {
    float y;
    asm("tanh.approx.f32 %0, %1;" : "=f"(y) : "f"(x));
    return y;
}
__device__ __forceinline__ float tanh_acc(float x) {
    float ax = fabsf(x);
    float t  = __expf(-2.0f * ax);
    float r  = __fdividef(1.0f - t, 1.0f + t);
    return copysignf(r, x);
}
__device__ __forceinline__ float sig_acc(float x) {
    return __fdividef(1.0f, 1.0f + __expf(-x));
}

// ---------------------------------------------------------------------------
// Tiny naive GEMM for the precompute tables (K=300 etc.)
// ---------------------------------------------------------------------------
__global__ void gemm_naive(const float* __restrict__ A, int lda,
                           const float* __restrict__ Bw, int ldb,
                           float* __restrict__ C, int ldc,
                           int M, int N, int K,
                           const float* __restrict__ bias) {
    int idx = blockIdx.x * blockDim.x + threadIdx.x;
    if (idx >= M * N) return;
    int m = idx / N, n = idx % N;
    float s = bias ? bias[n] : 0.0f;
    for (int k = 0; k < K; k++) s += A[m * lda + k] * Bw[k * ldb + n];
    C[m * ldc + n] = s;
}

// ---------------------------------------------------------------------------
// Main tiled GEMM v2: FFMA2 (fma.rn.f32x2) inner loop + register-staged
// double-buffered shared memory. Requires M%BM==0, N%BN==0, K%BK==0, TN even.
// Epilogue: C = act( acc + bias[n] + gtab[gidx[m]*ldg + n] )
// blockIdx.z==1 switches to a second identically-shaped problem.
// ---------------------------------------------------------------------------
template<int BM, int BN, int BK, int TM, int TN>
__global__ __launch_bounds__((BM/TM)*(BN/TN))
void gemm_k(const float* __restrict__ A, int lda,
            const float* __restrict__ Bw, int ldb,
            float* __restrict__ C, int ldc,
            int M, int N, int K,
            const float* __restrict__ bias,
            const float* __restrict__ gtab, const int* __restrict__ gidx, int ldg,
            int act,
            const float* __restrict__ A2, const float* __restrict__ B2,
            float* __restrict__ C2, const float* __restrict__ bias2) {
    constexpr int NT  = (BM / TM) * (BN / TN);
    constexpr int LA4 = (BM * BK) / (NT * 4);   // float4 A loads per thread
    constexpr int LB4 = (BK * BN) / (NT * 4);   // float4 B loads per thread
    constexpr int BMP = BM + 4;                 // pad to soften transpose-STS conflicts
    static_assert(LA4 >= 1 && LB4 >= 1, "tile too small");

    if (blockIdx.z == 1) { A = A2; Bw = B2; C = C2; bias = bias2; }

    __shared__ __align__(16) float As[2][BK][BMP];
    __shared__ __align__(16) float Bs[2][BK][BN];

    const int tid  = threadIdx.x;
    const int m0   = blockIdx.y * BM;
    const int n0   = blockIdx.x * BN;
    const int tcol = tid % (BN / TN);
    const int trow = tid / (BN / TN);

    float4 ra[LA4], rb[LB4];

    auto ldg_tile = [&](int k0) {
#pragma unroll
        for (int l = 0; l < LA4; l++) {
            int idx = tid + l * NT;
            int m = idx / (BK / 4), kq = idx % (BK / 4);
            ra[l] = *reinterpret_cast<const float4*>(&A[(size_t)(m0 + m) * lda + k0 + kq * 4]);
        }
#pragma unroll
        for (int l = 0; l < LB4; l++) {
            int idx = tid + l * NT;
            int kk = idx / (BN / 4), nq = idx % (BN / 4);
            rb[l] = *reinterpret_cast<const float4*>(&Bw[(size_t)(k0 + kk) * ldb + n0 + nq * 4]);
        }
    };
    auto sts_tile = [&](int buf) {
#pragma unroll
        for (int l = 0; l < LA4; l++) {
            int idx = tid + l * NT;
            int m = idx / (BK / 4), kq = idx % (BK / 4);
            As[buf][kq * 4 + 0][m] = ra[l].x;
            As[buf][kq * 4 + 1][m] = ra[l].y;
            As[buf][kq * 4 + 2][m] = ra[l].z;
            As[buf][kq * 4 + 3][m] = ra[l].w;
        }
#pragma unroll
        for (int l = 0; l < LB4; l++) {
            int idx = tid + l * NT;
            int kk = idx / (BN / 4), nq = idx % (BN / 4);
            *reinterpret_cast<float4*>(&Bs[buf][kk][nq * 4]) = rb[l];
        }
    };

    unsigned long long acc[TM][TN / 2];
#pragma unroll
    for (int i = 0; i < TM; i++)
#pragma unroll
        for (int j = 0; j < TN / 2; j++) acc[i][j] = 0ULL;   // two packed 0.0f

    ldg_tile(0);
    sts_tile(0);
    __syncthreads();

    const int nt = K / BK;
    for (int t = 0; t < nt; t++) {
        const int cur = t & 1;
        if (t + 1 < nt) ldg_tile((t + 1) * BK);

#pragma unroll
        for (int kk = 0; kk < BK; kk++) {
            float a[TM];
            unsigned long long b2[TN / 2];
#pragma unroll
            for (int i = 0; i < TM; i += 4) {
                float4 v = *reinterpret_cast<const float4*>(&As[cur][kk][trow * TM + i]);
                a[i + 0] = v.x; a[i + 1] = v.y; a[i + 2] = v.z; a[i + 3] = v.w;
            }
#pragma unroll
            for (int j = 0; j < TN; j += 4) {
                ulonglong2 v = *reinterpret_cast<const ulonglong2*>(&Bs[cur][kk][tcol * TN + j]);
                b2[j / 2]     = v.x;
                b2[j / 2 + 1] = v.y;
            }
#pragma unroll
            for (int i = 0; i < TM; i++) {
                unsigned long long a2;
                asm("mov.b64 %0, {%1, %1};" : "=l"(a2) : "f"(a[i]));
#pragma unroll
                for (int jj = 0; jj < TN / 2; jj++)
                    asm("fma.rn.f32x2 %0, %1, %2, %0;"
                        : "+l"(acc[i][jj]) : "l"(a2), "l"(b2[jj]));
            }
        }

        if (t + 1 < nt) sts_tile((t + 1) & 1);
        __syncthreads();
    }

#pragma unroll
    for (int i = 0; i < TM; i++) {
        int m = m0 + trow * TM + i;
        const float* grow = gtab ? (gtab + (size_t)gidx[m] * ldg) : nullptr;
#pragma unroll
        for (int jj = 0; jj < TN / 2; jj++) {
            float v0, v1;
            asm("mov.b64 {%0, %1}, %2;" : "=f"(v0), "=f"(v1) : "l"(acc[i][jj]));
            int n = n0 + tcol * TN + jj * 2;
            if (bias) { v0 += bias[n]; v1 += bias[n + 1]; }
            if (grow) { v0 += grow[n]; v1 += grow[n + 1]; }
            if (act == 1) { v0 = tanh_acc(v0); v1 = tanh_acc(v1); }
            *reinterpret_cast<float2*>(&C[(size_t)m * ldc + n]) = make_float2(v0, v1);
        }
    }
}

// ---------------------------------------------------------------------------
// Weight / bias concat builder for the fused decoder hidden GEMM
// ---------------------------------------------------------------------------
__global__ void build_wcat(const float* __restrict__ Wh,
                           const float* __restrict__ Whh,
                           const float* __restrict__ ab,
                           const float* __restrict__ bhh,
                           float* __restrict__ Wcat, float* __restrict__ bias_cat) {
    int idx = blockIdx.x * blockDim.x + threadIdx.x;
    if (idx < H * 1024) {
        int k = idx / 1024, n = idx % 1024;
        Wcat[idx] = (n < H) ? Wh[k * H + n] : Whh[k * G3 + (n - H)];
    }
    if (idx < 1024) bias_cat[idx] = (idx < H) ? ab[idx] : bhh[idx - H];
}

// ---------------------------------------------------------------------------
// Encoder GRU cell (both directions via blockIdx.z)
// ---------------------------------------------------------------------------
__global__ void enc_cell(const float* __restrict__ gh_f, const float* __restrict__ gh_b,
                         const float* __restrict__ emb_f, const float* __restrict__ emb_b,
                         const int* __restrict__ src, int s,
                         float* __restrict__ hf, float* __restrict__ hb,
                         float* __restrict__ enc_out) {
    int dir = blockIdx.z;
    int idx = blockIdx.x * blockDim.x + threadIdx.x;
    int b = idx >> 8;
    int h = idx & 255;
    int s_in = dir ? (S - 1 - s) : s;
    int tok  = src[s_in * B + b];
    const float* gh = (dir ? gh_b : gh_f) + (size_t)b * G3;
    const float* gi = (dir ? emb_b : emb_f) + (size_t)tok * G3;
    float* hp = (dir ? hb : hf) + (size_t)b * H + h;
    float r = sig_acc(gi[h] + gh[h]);
    float z = sig_acc(gi[H + h] + gh[H + h]);
    float n = tanh_acc(gi[2 * H + h] + r * gh[2 * H + h]);
    float hprev = *hp;
    float hn = (1.0f - z) * n + z * hprev;
    *hp = hn;
    enc_out[((size_t)b * S + s_in) * H2 + dir * H + h] = hn;
}

// ---------------------------------------------------------------------------
// Decoder GRU cell
// ---------------------------------------------------------------------------
__global__ void dec_cell(const float* __restrict__ g1, const float* __restrict__ gi,
                         float* __restrict__ h, float* __restrict__ xcat) {
    int idx = blockIdx.x * blockDim.x + threadIdx.x;
    int b = idx >> 8;
    int hh = idx & 255;
    const float* gh  = g1 + (size_t)b * 1024 + H;
    const float* gip = gi + (size_t)b * G3;
    float r = sig_acc(gip[hh] + gh[hh]);
    float z = sig_acc(gip[H + hh] + gh[H + hh]);
    float n = tanh_acc(gip[2 * H + hh] + r * gh[2 * H + hh]);
    float hprev = h[(size_t)b * H + hh];
    float hn = (1.0f - z) * n + z * hprev;
    h[(size_t)b * H + hh] = hn;
    xcat[(size_t)b * G3 + hh] = hn;
}

// ---------------------------------------------------------------------------
// Attention: one block per batch row
// ---------------------------------------------------------------------------
__global__ __launch_bounds__(256)
void attn_k(const float* __restrict__ g1, const float* __restrict__ proj,
            const float* __restrict__ enc_out, const float* __restrict__ v,
            float* __restrict__ weighted, float* __restrict__ xcat) {
    int b = blockIdx.x;
    int tid = threadIdx.x;
    __shared__ float e_sh[S];
    __shared__ float a_sh[S];
    __shared__ float red[8];

    float q  = g1[(size_t)b * 1024 + tid];
    float vv = v[tid];
    const float* prow = proj + (size_t)b * S * H;

    for (int s = 0; s < S; s++) {
        float x = q + prow[s * H + tid];
        float val = vv * tanh_approx(x);
#pragma unroll
        for (int o = 16; o > 0; o >>= 1) val += __shfl_xor_sync(0xffffffffu, val, o);
        if ((tid & 31) == 0) red[tid >> 5] = val;
        __syncthreads();
        if (tid < 8) {
            float r2 = red[tid];
#pragma unroll
            for (int o = 4; o > 0; o >>= 1) r2 += __shfl_xor_sync(0xffu, r2, o);
            if (tid == 0) e_sh[s] = r2;
        }
        __syncthreads();
    }

    if (tid < 32) {
        float x = (tid < S) ? e_sh[tid] : -1e30f;
        float mx = x;
#pragma unroll
        for (int o = 16; o > 0; o >>= 1) mx = fmaxf(mx, __shfl_xor_sync(0xffffffffu, mx, o));
        float ex = (tid < S) ? __expf(x - mx) : 0.0f;
        float sm = ex;
#pragma unroll
        for (int o = 16; o > 0; o >>= 1) sm += __shfl_xor_sync(0xffffffffu, sm, o);
        if (tid < S) a_sh[tid] = __fdividef(ex, sm);
    }
    __syncthreads();

    const float* orow = enc_out + (size_t)b * S * H2;
    for (int d = tid; d < H2; d += 256) {
        float acc = 0.0f;
#pragma unroll
        for (int s = 0; s < S; s++) acc = fmaf(a_sh[s], orow[s * H2 + d], acc);
        weighted[(size_t)b * H2 + d] = acc;
        xcat[(size_t)b * G3 + H + d] = acc;
    }
}

__global__ void concat_h(const float* __restrict__ hf, const float* __restrict__ hb,
                         float* __restrict__ cat) {
    int idx = blockIdx.x * blockDim.x + threadIdx.x;
    int b = idx >> 9, j = idx & 511;
    cat[idx] = (j < H) ? hf[b * H + j] : hb[b * H + (j - H)];
}

// ---------------------------------------------------------------------------
// Host-side launch helpers
// ---------------------------------------------------------------------------
static void gemm128(const float* A, int lda, const float* Bw, int ldb,
                    float* C, int ldc, int M, int N, int K,
                    const float* bias, const float* gtab, const int* gidx, int ldg,
                    int act,
                    const float* A2 = nullptr, const float* B2 = nullptr,
                    float* C2 = nullptr, const float* bias2 = nullptr) {
    dim3 g(N / 128, M / 128, A2 ? 2 : 1);
    gemm_k<128, 128, 16, 8, 8><<<g, 256>>>(A, lda, Bw, ldb, C, ldc, M, N, K,
                                           bias, gtab, gidx, ldg, act, A2, B2, C2, bias2);
}
static void gemm64(const float* A, int lda, const float* Bw, int ldb,
                   float* C, int ldc, int M, int N, int K,
                   const float* bias, const float* gtab, const int* gidx, int ldg,
                   int act) {
    dim3 g(N / 64, M / 64, 1);
    gemm_k<64, 64, 16, 4, 4><<<g, 256>>>(A, lda, Bw, ldb, C, ldc, M, N, K,
                                         bias, gtab, gidx, ldg, act,
                                         nullptr, nullptr, nullptr, nullptr);
}
static void gemm32(const float* A, int lda, const float* Bw, int ldb,
                   float* C, int ldc, int M, int N, int K,
                   const float* bias, const float* gtab, const int* gidx, int ldg,
                   int act) {
    dim3 g(N / 64, M / 32, 1);
    gemm_k<32, 64, 16, 4, 4><<<g, 128>>>(A, lda, Bw, ldb, C, ldc, M, N, K,
                                         bias, gtab, gidx, ldg, act,
                                         nullptr, nullptr, nullptr, nullptr);
}

extern "C" void kernel_launch(void* const* d_in, const int* in_sizes, int n_in,
                              void* d_out, int out_size) {
    const int*   src       = (const int*)  d_in[0];
    const int*   trg       = (const int*)  d_in[1];
    const float* enc_emb   = (const float*)d_in[2];
    const float* enc_Wih_f = (const float*)d_in[3];
    const float* enc_Whh_f = (const float*)d_in[4];
    const float* enc_bih_f = (const float*)d_in[5];
    const float* enc_bhh_f = (const float*)d_in[6];
    const float* enc_Wih_b = (const float*)d_in[7];
    const float* enc_Whh_b = (const float*)d_in[8];
    const float* enc_bih_b = (const float*)d_in[9];
    const float* enc_bhh_b = (const float*)d_in[10];
    const float* enc_fcW   = (const float*)d_in[11];
    const float* enc_fcb   = (const float*)d_in[12];
    const float* attn_Wh   = (const float*)d_in[13];
    const float* attn_We   = (const float*)d_in[14];
    const float* attn_b    = (const float*)d_in[15];
    const float* attn_v    = (const float*)d_in[16];
    const float* dec_emb   = (const float*)d_in[17];
    const float* dec_Wih   = (const float*)d_in[18];
    const float* dec_Whh   = (const float*)d_in[19];
    const float* dec_bih   = (const float*)d_in[20];
    const float* dec_bhh   = (const float*)d_in[21];
    const float* fcW       = (const float*)d_in[22];
    const float* fcb       = (const float*)d_in[23];
    float* out = (float*)d_out;

    float *p_emb_gi_f, *p_emb_gi_b, *p_dec_gi_emb, *p_dec_logit_emb;
    float *p_Wcat, *p_bias_cat, *p_hf, *p_hb, *p_h, *p_cat512;
    float *p_enc_out, *p_enc_proj, *p_gh, *p_g1, *p_gi, *p_weighted, *p_xcat;
    void* tmp;
    cudaGetSymbolAddress(&tmp, g_emb_gi_f);      p_emb_gi_f     = (float*)tmp;
    cudaGetSymbolAddress(&tmp, g_emb_gi_b);      p_emb_gi_b     = (float*)tmp;
    cudaGetSymbolAddress(&tmp, g_dec_gi_emb);    p_dec_gi_emb   = (float*)tmp;
    cudaGetSymbolAddress(&tmp, g_dec_logit_emb); p_dec_logit_emb= (float*)tmp;
    cudaGetSymbolAddress(&tmp, g_Wcat);          p_Wcat         = (float*)tmp;
    cudaGetSymbolAddress(&tmp, g_bias_cat);      p_bias_cat     = (float*)tmp;
    cudaGetSymbolAddress(&tmp, g_hf);            p_hf           = (float*)tmp;
    cudaGetSymbolAddress(&tmp, g_hb);            p_hb           = (float*)tmp;
    cudaGetSymbolAddress(&tmp, g_h);             p_h            = (float*)tmp;
    cudaGetSymbolAddress(&tmp, g_cat512);        p_cat512       = (float*)tmp;
    cudaGetSymbolAddress(&tmp, g_enc_out);       p_enc_out      = (float*)tmp;
    cudaGetSymbolAddress(&tmp, g_enc_proj);      p_enc_proj     = (float*)tmp;
    cudaGetSymbolAddress(&tmp, g_gh);            p_gh           = (float*)tmp;
    cudaGetSymbolAddress(&tmp, g_g1);            p_g1           = (float*)tmp;
    cudaGetSymbolAddress(&tmp, g_gi);            p_gi           = (float*)tmp;
    cudaGetSymbolAddress(&tmp, g_weighted);      p_weighted     = (float*)tmp;
    cudaGetSymbolAddress(&tmp, g_xcat);          p_xcat         = (float*)tmp;

    // ---- precompute tables ----
    gemm_naive<<<(VIN * G3 + 255) / 256, 256>>>(enc_emb, E, enc_Wih_f, G3,
                                                p_emb_gi_f, G3, VIN, G3, E, enc_bih_f);
    gemm_naive<<<(VIN * G3 + 255) / 256, 256>>>(enc_emb, E, enc_Wih_b, G3,
                                                p_emb_gi_b, G3, VIN, G3, E, enc_bih_b);
    gemm_naive<<<(VOUT * G3 + 255) / 256, 256>>>(dec_emb, E, dec_Wih, G3,
                                                 p_dec_gi_emb, G3, VOUT, G3, E, dec_bih);
    gemm_naive<<<(VOUT * VOUT + 255) / 256, 256>>>(dec_emb, E, fcW + (size_t)G3 * VOUT, VOUT,
                                                   p_dec_logit_emb, VOUT, VOUT, VOUT, E, fcb);
    build_wcat<<<(H * 1024 + 255) / 256, 256>>>(attn_Wh, dec_Whh, attn_b, dec_bhh,
                                                p_Wcat, p_bias_cat);
    cudaMemsetAsync(p_hf, 0, (size_t)B * H * sizeof(float));
    cudaMemsetAsync(p_hb, 0, (size_t)B * H * sizeof(float));
    cudaMemsetAsync(out, 0, (size_t)B * VOUT * sizeof(float));

    // ---- encoder: 24 steps, fwd+bwd fused via grid.z ----
    for (int s = 0; s < S; s++) {
        gemm128(p_hf, H, enc_Whh_f, G3, p_gh, G3, B, G3, H,
                enc_bhh_f, nullptr, nullptr, 0, 0,
                p_hb, enc_Whh_b, p_gh + (size_t)B * G3, enc_bhh_b);
        enc_cell<<<dim3(B * H / 256, 1, 2), 256>>>(p_gh, p_gh + (size_t)B * G3,
                                                   p_emb_gi_f, p_emb_gi_b,
                                                   src, s, p_hf, p_hb, p_enc_out);
    }

    // ---- decoder init hidden ----
    concat_h<<<B * H2 / 256, 256>>>(p_hf, p_hb, p_cat512);
    gemm64(p_cat512, H2, enc_fcW, H, p_h, H, B, H, H2, enc_fcb,
           nullptr, nullptr, 0, /*tanh*/1);

    // ---- enc_proj = enc_out @ attn_We ----
    gemm128(p_enc_out, H2, attn_We, H, p_enc_proj, H, B * S, H, H2,
            nullptr, nullptr, nullptr, 0, 0);

    // ---- decoder: 24 steps ----
    for (int t = 0; t < T - 1; t++) {
        const int* tok = trg + t * B;
        gemm128(p_h, H, p_Wcat, 1024, p_g1, 1024, B, 1024, H,
                p_bias_cat, nullptr, nullptr, 0, 0);
        attn_k<<<B, 256>>>(p_g1, p_enc_proj, p_enc_out, attn_v, p_weighted, p_xcat);
        gemm128(p_weighted, H2, dec_Wih + (size_t)E * G3, G3, p_gi, G3, B, G3, H2,
                nullptr, p_dec_gi_emb, tok, G3, 0);
        dec_cell<<<B * H / 256, 256>>>(p_g1, p_gi, p_h, p_xcat);
        gemm32(p_xcat, G3, fcW, VOUT, out + (size_t)(t + 1) * B * VOUT, VOUT,
               B, VOUT, G3, nullptr, p_dec_logit_emb, tok, VOUT, 0);
    }
}